// round 14
// baseline (speedup 1.0000x reference)
#include <cuda_runtime.h>

#define N_ITEMS 20000
#define ALPHA 0.2f
#define GRID 760              // 5 CTAs/SM x 152 SMs (persistent)
#define SROW (GRID * 64)      // element stride per grid step

#define CP16(dst_u32, src_ptr) \
    asm volatile("cp.async.cg.shared.global [%0], [%1], 16;" :: "r"(dst_u32), "l"(src_ptr))
#define CPCOMMIT() asm volatile("cp.async.commit_group;" ::: "memory")
#define CPWAIT0()  asm volatile("cp.async.wait_group 0;"  ::: "memory")

__global__ __launch_bounds__(256, 5) void gat_kernel(
    const float* __restrict__ item,
    const float* __restrict__ ent,
    const int*   __restrict__ adj,
    const float* __restrict__ W,
    const float* __restrict__ a,
    float*       __restrict__ out)
{
    __shared__ float4 tile[2][1024];   // 2 x 16KB ring
    __shared__ float wa1s[64], wa2s[64];
    __shared__ float xbuf[64];
    __shared__ float part[512];
    __shared__ float s1buf[2];
    __shared__ float smInv[2];

    const int t    = threadIdx.x;
    const int lane = t & 31;
    const int w    = t >> 5;
    const int q    = t & 15;            // f4 index within row
    const int mB   = t >> 4;            // 0..15
    const int fe   = (w - 4) * 32 + lane;  // epilogue f (warps 4-5)
    const int mrow = mB + 16 * (lane & 3); // row whose d this lane holds post-fold

    // --- wa1 = W@a1, wa2 = W@a2; zero tile buffers (once) ---
    {
        const int f = t >> 2, qq = t & 3;
        const float* wr = W + f * 64 + qq * 16;
        float p1 = 0.f, p2 = 0.f;
#pragma unroll
        for (int i = 0; i < 4; ++i) {
            float4 wv = *(const float4*)(wr + i * 4);
            float4 y1 = *(const float4*)(a + qq * 16 + i * 4);
            float4 y2 = *(const float4*)(a + 64 + qq * 16 + i * 4);
            p1 += wv.x*y1.x + wv.y*y1.y + wv.z*y1.z + wv.w*y1.w;
            p2 += wv.x*y2.x + wv.y*y2.y + wv.z*y2.z + wv.w*y2.w;
        }
        p1 += __shfl_xor_sync(~0u, p1, 1); p1 += __shfl_xor_sync(~0u, p1, 2);
        p2 += __shfl_xor_sync(~0u, p2, 1); p2 += __shfl_xor_sync(~0u, p2, 2);
        if (qq == 0) { wa1s[f] = p1; wa2s[f] = p2; }
        const float4 z = make_float4(0.f, 0.f, 0.f, 0.f);
#pragma unroll
        for (int c = 0; c < 4; ++c) { tile[0][t + 256*c] = z; tile[1][t + 256*c] = z; }
    }
    __syncthreads();
    const float4 w2   = *(const float4*)&wa2s[q * 4];
    const float  wa1a = wa1s[lane];
    const float  wa1b = wa1s[32 + lane];
    const unsigned sb = (unsigned)__cvta_generic_to_shared(&tile[0][0]);

    int n   = blockIdx.x;
    int off = n * 64;

    // --- Prime: masks row n, cp.async tile n -> buf0, masks row n+1, s1 row n ---
    unsigned bm0, bm1, nx0 = 0, nx1 = 0;
    {
        const int a0 = adj[off + lane], a1 = adj[off + 32 + lane];
        bm0 = __ballot_sync(~0u, a0 > 0);
        bm1 = __ballot_sync(~0u, a1 > 0);
    }
    {
        const float* eb = ent + (size_t)off * 64;
#pragma unroll
        for (int c = 0; c < 4; ++c) {
            const int m = mB + 16 * c;
            const bool lv = (m < 32) ? ((bm0 >> m) & 1u) : ((bm1 >> (m - 32)) & 1u);
            if (lv) CP16(sb + (t + 256*c) * 16, eb + (size_t)(t + 256*c) * 4);
        }
        CPCOMMIT();
    }
    bool hasN = (n + GRID) < N_ITEMS;
    if (hasN) {
        const int a0 = adj[off + SROW + lane], a1 = adj[off + SROW + 32 + lane];
        nx0 = __ballot_sync(~0u, a0 > 0);
        nx1 = __ballot_sync(~0u, a1 > 0);
    }
    float ia = 0.f, ib = 0.f, iePrev = 0.f, ieCur = 0.f;
    if (w == 2) {
        ia = item[off + lane]; ib = item[off + 32 + lane];
        float p = ia * wa1a + ib * wa1b;
        p += __shfl_xor_sync(~0u, p, 16);
        p += __shfl_xor_sync(~0u, p, 8);
        p += __shfl_xor_sync(~0u, p, 4);
        p += __shfl_xor_sync(~0u, p, 2);
        p += __shfl_xor_sync(~0u, p, 1);
        if (lane == 0) s1buf[0] = p;
        if (hasN) { ia = item[off + SROW + lane]; ib = item[off + SROW + 32 + lane]; }
    }
    if (w == 4 || w == 5) ieCur = item[off + fe];

    int par = 0, offPrev = -1;

    while (true) {
        CPWAIT0();
        __syncthreads();   // BAR1: tile[par] staged; prev window-C writes visible

        // ==== Window M ====
        // 1) issue NEXT tile into buf[par^1] immediately (max async distance)
        if (hasN) {
            const float* ebN = ent + (size_t)(off + SROW) * 64;
            const unsigned dstb = sb + (unsigned)(par ^ 1) * 16384u;
#pragma unroll
            for (int c = 0; c < 4; ++c) {
                const int m = mB + 16 * c;
                const bool lv = (m < 32) ? ((nx0 >> m) & 1u) : ((nx1 >> (m - 32)) & 1u);
                if (lv) CP16(dstb + (t + 256*c) * 16, ebN + (size_t)(t + 256*c) * 4);
            }
        }
        CPCOMMIT();

        // 2) read tile[par] (kept in regs through acc), d-phase fold
        float4 v[4];
#pragma unroll
        for (int c = 0; c < 4; ++c) v[c] = tile[par][t + 256*c];
        float dd[4];
#pragma unroll
        for (int c = 0; c < 4; ++c)
            dd[c] = v[c].x*w2.x + v[c].y*w2.y + v[c].z*w2.z + v[c].w*w2.w;
        float h0 = ((lane&1)? dd[1]:dd[0]) + __shfl_xor_sync(~0u, (lane&1)? dd[0]:dd[1], 1);
        float h1 = ((lane&1)? dd[3]:dd[2]) + __shfl_xor_sync(~0u, (lane&1)? dd[2]:dd[3], 1);
        float g  = ((lane&2)? h1:h0)       + __shfl_xor_sync(~0u, (lane&2)? h0:h1, 2);
        g += __shfl_xor_sync(~0u, g, 4);
        g += __shfl_xor_sync(~0u, g, 8);

        float e = s1buf[par] + g;
        e = fmaxf(e, ALPHA * e);
        const unsigned mbit = (mrow < 32) ? ((bm0 >> mrow) & 1u) : ((bm1 >> (mrow - 32)) & 1u);
        const float x = mbit ? __expf(e) : 0.f;
        if (!(lane & 12)) xbuf[mrow] = x;

        // 3) side jobs
        if (w == 2 && hasN) {     // s1 for next row
            float p = ia * wa1a + ib * wa1b;
            p += __shfl_xor_sync(~0u, p, 16);
            p += __shfl_xor_sync(~0u, p, 8);
            p += __shfl_xor_sync(~0u, p, 4);
            p += __shfl_xor_sync(~0u, p, 2);
            p += __shfl_xor_sync(~0u, p, 1);
            if (lane == 0) s1buf[par ^ 1] = p;
            if ((n + 2 * GRID) < N_ITEMS) {
                ia = item[off + 2 * SROW + lane];
                ib = item[off + 2 * SROW + 32 + lane];
            }
        }
        if (w == 4 || w == 5) {   // epilogue for previous row
            if (offPrev >= 0) {
                const float r = ((part[fe]       + part[64 + fe])
                              +  (part[128 + fe] + part[192 + fe]))
                              + ((part[256 + fe] + part[320 + fe])
                              +  (part[384 + fe] + part[448 + fe]));
                out[offPrev + fe] = r * smInv[par ^ 1] + iePrev;
            }
            iePrev = ieCur;
            if (hasN) ieCur = item[off + SROW + fe];
        }
        __syncthreads();   // BAR2: xbuf ready

        // ==== Window C ====
        {
            float4 acc;
            const float x0 = xbuf[mB];
            acc.x = x0 * v[0].x; acc.y = x0 * v[0].y;
            acc.z = x0 * v[0].z; acc.w = x0 * v[0].w;
#pragma unroll
            for (int c = 1; c < 4; ++c) {
                const float xv = xbuf[mB + 16 * c];
                acc.x = fmaf(xv, v[c].x, acc.x);
                acc.y = fmaf(xv, v[c].y, acc.y);
                acc.z = fmaf(xv, v[c].z, acc.z);
                acc.w = fmaf(xv, v[c].w, acc.w);
            }
            acc.x += __shfl_xor_sync(~0u, acc.x, 16);
            acc.y += __shfl_xor_sync(~0u, acc.y, 16);
            acc.z += __shfl_xor_sync(~0u, acc.z, 16);
            acc.w += __shfl_xor_sync(~0u, acc.w, 16);
            if (lane < 16) *(float4*)&part[w * 64 + lane * 4] = acc;
        }
        if (w == 0) {   // sum of x -> 1/sum (single warp)
            float s = xbuf[lane] + xbuf[32 + lane];
            s += __shfl_xor_sync(~0u, s, 16);
            s += __shfl_xor_sync(~0u, s, 8);
            s += __shfl_xor_sync(~0u, s, 4);
            s += __shfl_xor_sync(~0u, s, 2);
            s += __shfl_xor_sync(~0u, s, 1);
            if (lane == 0) smInv[par] = 1.0f / s;
        }
        // masks for row n+2
        bm0 = nx0; bm1 = nx1;
        const bool hasNN = (n + 2 * GRID) < N_ITEMS;
        if (hasNN) {
            const int a0 = adj[off + 2 * SROW + lane];
            const int a1 = adj[off + 2 * SROW + 32 + lane];
            nx0 = __ballot_sync(~0u, a0 > 0);
            nx1 = __ballot_sync(~0u, a1 > 0);
        } else { nx0 = 0; nx1 = 0; }

        offPrev = off; off += SROW; n += GRID; par ^= 1; hasN = hasNN;
        if (n >= N_ITEMS) break;
    }

    // ---- drain: epilogue for the final row ----
    __syncthreads();
    if (w == 4 || w == 5) {
        const float r = ((part[fe]       + part[64 + fe])
                      +  (part[128 + fe] + part[192 + fe]))
                      + ((part[256 + fe] + part[320 + fe])
                      +  (part[384 + fe] + part[448 + fe]));
        out[offPrev + fe] = r * smInv[par ^ 1] + iePrev;
    }
}

extern "C" void kernel_launch(void* const* d_in, const int* in_sizes, int n_in,
                              void* d_out, int out_size) {
    const float* item = (const float*)d_in[0];
    const float* ent  = (const float*)d_in[1];
    const int*   adj  = (const int*)d_in[2];
    const float* W    = (const float*)d_in[3];
    const float* a    = (const float*)d_in[4];
    float* out = (float*)d_out;

    gat_kernel<<<GRID, 256>>>(item, ent, adj, W, a, out);
}

// round 15
// speedup vs baseline: 1.1283x; 1.1283x over previous
#include <cuda_runtime.h>

#define N_ITEMS 20000
#define ALPHA 0.2f
#define GRID 608               // 4 CTAs/SM x 152 SMs (persistent)
#define NGROUP (GRID * 2)      // 1216 independent row pipelines
#define S64 (NGROUP * 64)

#define BARG() asm volatile("bar.sync %0, 128;" :: "r"(barid) : "memory")

__global__ __launch_bounds__(256, 4) void gat_kernel(
    const float* __restrict__ item,
    const float* __restrict__ ent,
    const int*   __restrict__ adj,
    const float* __restrict__ W,
    const float* __restrict__ a,
    float*       __restrict__ out)
{
    __shared__ float wa1s[64], wa2s[64];
    __shared__ float dbuf[2][64];
    __shared__ float xbuf[2][64];
    __shared__ float part[2][512];      // 8 half-warp partials x 64 f
    __shared__ float smsum[2][2][2];    // [group][parity][warp 0/1]
    __shared__ float s1buf[2][2];       // [group][parity]

    const int t    = threadIdx.x;
    const int gi   = t >> 7;
    const int gt   = t & 127;
    const int lane = t & 31;
    const int wg   = gt >> 5;
    const int mB   = gt >> 4;          // 0..7
    const int fs   = lane & 15;
    const int fe   = gt - 64;          // epilogue f (wg>=2)
    const int barid = 1 + gi;

    // --- wa1 = W@a1, wa2 = W@a2 (once per CTA) ---
    {
        const int f = t >> 2, q = t & 3;
        const float* wr = W + f * 64 + q * 16;
        float p1 = 0.f, p2 = 0.f;
#pragma unroll
        for (int i = 0; i < 4; ++i) {
            float4 wv = *(const float4*)(wr + i * 4);
            float4 y1 = *(const float4*)(a + q * 16 + i * 4);
            float4 y2 = *(const float4*)(a + 64 + q * 16 + i * 4);
            p1 += wv.x*y1.x + wv.y*y1.y + wv.z*y1.z + wv.w*y1.w;
            p2 += wv.x*y2.x + wv.y*y2.y + wv.z*y2.z + wv.w*y2.w;
        }
        p1 += __shfl_xor_sync(~0u, p1, 1); p1 += __shfl_xor_sync(~0u, p1, 2);
        p2 += __shfl_xor_sync(~0u, p2, 1); p2 += __shfl_xor_sync(~0u, p2, 2);
        if (q == 0) { wa1s[f] = p1; wa2s[f] = p2; }
    }
    __syncthreads();
    const float4 w2   = *(const float4*)&wa2s[fs * 4];
    const float  wa1a = wa1s[lane];
    const float  wa1b = wa1s[32 + lane];

    int n   = blockIdx.x * 2 + gi;
    int off = n * 64;

    // --- Prime row n: masks + tile; masks for n+1; s1(row n) by wg2 ---
    unsigned bm0, bm1, nx0 = 0, nx1 = 0;
    {
        const int a0 = adj[off + lane], a1 = adj[off + 32 + lane];
        bm0 = __ballot_sync(~0u, a0 > 0);
        bm1 = __ballot_sync(~0u, a1 > 0);
    }
    float4 v[8];
    {
        const float* eb = ent + (size_t)off * 64;
#pragma unroll
        for (int c = 0; c < 8; ++c) {
            const int m = mB + 8 * c;
            const bool lv = (m < 32) ? ((bm0 >> m) & 1u) : ((bm1 >> (m - 32)) & 1u);
            v[c] = lv ? *(const float4*)(eb + (size_t)(gt + 128 * c) * 4)
                      : make_float4(0.f, 0.f, 0.f, 0.f);
        }
    }
    bool hasN = (n + NGROUP) < N_ITEMS;
    if (hasN) {
        const int a0 = adj[off + S64 + lane], a1 = adj[off + S64 + 32 + lane];
        nx0 = __ballot_sync(~0u, a0 > 0);
        nx1 = __ballot_sync(~0u, a1 > 0);
    }
    float ia = 0.f, ib = 0.f, iePrev = 0.f, ieCur = 0.f;
    if (wg == 2) {
        ia = item[off + lane]; ib = item[off + 32 + lane];
        float p = ia * wa1a + ib * wa1b;
        p += __shfl_xor_sync(~0u, p, 16);
        p += __shfl_xor_sync(~0u, p, 8);
        p += __shfl_xor_sync(~0u, p, 4);
        p += __shfl_xor_sync(~0u, p, 2);
        p += __shfl_xor_sync(~0u, p, 1);
        if (lane == 0) s1buf[gi][0] = p;
        if (hasN) { ia = item[off + S64 + lane]; ib = item[off + S64 + 32 + lane]; }
    }
    if (wg >= 2) ieCur = item[off + fe];

    int par = 0, offPrev = -1;

    while (true) {
        // ==== Window A: pure d-phase (all warps) ====
        float dd[8];
#pragma unroll
        for (int c = 0; c < 8; ++c)
            dd[c] = v[c].x*w2.x + v[c].y*w2.y + v[c].z*w2.z + v[c].w*w2.w;
        float e0 = ((lane&1)? dd[1]:dd[0]) + __shfl_xor_sync(~0u, (lane&1)? dd[0]:dd[1], 1);
        float e1 = ((lane&1)? dd[3]:dd[2]) + __shfl_xor_sync(~0u, (lane&1)? dd[2]:dd[3], 1);
        float e2 = ((lane&1)? dd[5]:dd[4]) + __shfl_xor_sync(~0u, (lane&1)? dd[4]:dd[5], 1);
        float e3 = ((lane&1)? dd[7]:dd[6]) + __shfl_xor_sync(~0u, (lane&1)? dd[6]:dd[7], 1);
        float f0 = ((lane&2)? e1:e0) + __shfl_xor_sync(~0u, (lane&2)? e0:e1, 2);
        float f1 = ((lane&2)? e3:e2) + __shfl_xor_sync(~0u, (lane&2)? e2:e3, 2);
        float g0 = ((lane&4)? f1:f0) + __shfl_xor_sync(~0u, (lane&4)? f0:f1, 4);
        g0 += __shfl_xor_sync(~0u, g0, 8);
        if (!(lane & 8)) dbuf[gi][mB + 8 * (lane & 7)] = g0;
        BARG();

        // ==== Window B: wg0/1: x only; wg2/3: prev epilogue + item prefetch ====
        float x = 0.f;
        if (wg < 2) {
            float e = s1buf[gi][par] + dbuf[gi][gt];
            e = fmaxf(e, ALPHA * e);
            const unsigned mk = wg ? bm1 : bm0;
            x = ((mk >> lane) & 1u) ? __expf(e) : 0.f;
            xbuf[gi][gt] = x;
        } else {
            if (offPrev >= 0) {
                const int pp = par ^ 1;
                const float r = ((part[gi][fe]       + part[gi][64 + fe])
                              +  (part[gi][128 + fe] + part[gi][192 + fe]))
                              + ((part[gi][256 + fe] + part[gi][320 + fe])
                              +  (part[gi][384 + fe] + part[gi][448 + fe]));
                const float inv = 1.0f / (smsum[gi][pp][0] + smsum[gi][pp][1]);
                out[offPrev + fe] = r * inv + iePrev;
            }
            iePrev = ieCur;
            if (hasN) {
                ieCur = item[off + S64 + fe];
                if (wg == 2) { ia = item[off + S64 + lane]; ib = item[off + S64 + 32 + lane]; }
            }
        }
        BARG();

        // ==== Window C: acc + next tile LDGs + deferred shfl chains ====
        const bool hasNN = (n + 2 * NGROUP) < N_ITEMS;
        {
            const float* ebN = ent + (size_t)(off + S64) * 64;
            float4 acc;
            const float x0 = xbuf[gi][mB];
            acc.x = x0 * v[0].x; acc.y = x0 * v[0].y;
            acc.z = x0 * v[0].z; acc.w = x0 * v[0].w;
            {
                const int m = mB;
                const bool lv = hasN && ((m < 32) ? ((nx0 >> m) & 1u) : ((nx1 >> (m - 32)) & 1u));
                v[0] = lv ? *(const float4*)(ebN + (size_t)gt * 4)
                          : make_float4(0.f, 0.f, 0.f, 0.f);
            }
#pragma unroll
            for (int c = 1; c < 8; ++c) {
                const float xv = xbuf[gi][mB + 8 * c];
                acc.x = fmaf(xv, v[c].x, acc.x);
                acc.y = fmaf(xv, v[c].y, acc.y);
                acc.z = fmaf(xv, v[c].z, acc.z);
                acc.w = fmaf(xv, v[c].w, acc.w);
                const int m = mB + 8 * c;
                const bool lv = hasN && ((m < 32) ? ((nx0 >> m) & 1u)
                                                  : ((nx1 >> (m - 32)) & 1u));
                v[c] = lv ? *(const float4*)(ebN + (size_t)(gt + 128 * c) * 4)
                          : make_float4(0.f, 0.f, 0.f, 0.f);
            }
            // both m-halves stored; epilogue sums 8 (no shfl16 chain)
            *(float4*)&part[gi][mB * 64 + fs * 4] = acc;
        }
        // deferred: Sum(x) for current row (wg0/1, x still in reg)
        if (wg < 2) {
            float sm = x;
            sm += __shfl_xor_sync(~0u, sm, 16);
            sm += __shfl_xor_sync(~0u, sm, 8);
            sm += __shfl_xor_sync(~0u, sm, 4);
            sm += __shfl_xor_sync(~0u, sm, 2);
            sm += __shfl_xor_sync(~0u, sm, 1);
            if (lane == 0) smsum[gi][par][wg] = sm;
        }
        // deferred: s1 for next row (wg2, ia/ib prefetched in window B)
        if (wg == 2 && hasN) {
            float p = ia * wa1a + ib * wa1b;
            p += __shfl_xor_sync(~0u, p, 16);
            p += __shfl_xor_sync(~0u, p, 8);
            p += __shfl_xor_sync(~0u, p, 4);
            p += __shfl_xor_sync(~0u, p, 2);
            p += __shfl_xor_sync(~0u, p, 1);
            if (lane == 0) s1buf[gi][par ^ 1] = p;
        }
        // masks for row n+2
        bm0 = nx0; bm1 = nx1;
        if (hasNN) {
            const int a0 = adj[off + 2 * S64 + lane];
            const int a1 = adj[off + 2 * S64 + 32 + lane];
            nx0 = __ballot_sync(~0u, a0 > 0);
            nx1 = __ballot_sync(~0u, a1 > 0);
        } else { nx0 = 0; nx1 = 0; }

        offPrev = off; off += S64; n += NGROUP; par ^= 1; hasN = hasNN;
        if (n >= N_ITEMS) break;
    }

    // ---- drain: epilogue for the final row ----
    BARG();
    if (wg >= 2) {
        const int pp = par ^ 1;
        const float r = ((part[gi][fe]       + part[gi][64 + fe])
                      +  (part[gi][128 + fe] + part[gi][192 + fe]))
                      + ((part[gi][256 + fe] + part[gi][320 + fe])
                      +  (part[gi][384 + fe] + part[gi][448 + fe]));
        const float inv = 1.0f / (smsum[gi][pp][0] + smsum[gi][pp][1]);
        out[offPrev + fe] = r * inv + iePrev;
    }
}

extern "C" void kernel_launch(void* const* d_in, const int* in_sizes, int n_in,
                              void* d_out, int out_size) {
    const float* item = (const float*)d_in[0];
    const float* ent  = (const float*)d_in[1];
    const int*   adj  = (const int*)d_in[2];
    const float* W    = (const float*)d_in[3];
    const float* a    = (const float*)d_in[4];
    float* out = (float*)d_out;

    gat_kernel<<<GRID, 256>>>(item, ent, adj, W, a, out);
}

// round 16
// speedup vs baseline: 1.1413x; 1.0115x over previous
#include <cuda_runtime.h>

#define N_ITEMS 20000
#define ALPHA 0.2f
#define GRID 608               // 4 CTAs/SM x 152 SMs (persistent)
#define NGROUP (GRID * 2)      // 1216 independent row pipelines
#define S64 (NGROUP * 64)

#define BARG() asm volatile("bar.sync %0, 128;" :: "r"(barid) : "memory")

typedef unsigned long long u64;

__device__ __forceinline__ u64 pk2(float lo, float hi) {
    u64 r; asm("mov.b64 %0, {%1,%2};" : "=l"(r) : "f"(lo), "f"(hi)); return r;
}
__device__ __forceinline__ float2 unpk2(u64 p) {
    float2 r; asm("mov.b64 {%0,%1}, %2;" : "=f"(r.x), "=f"(r.y) : "l"(p)); return r;
}
__device__ __forceinline__ u64 mul2(u64 a, u64 b) {
    u64 r; asm("mul.f32x2 %0, %1, %2;" : "=l"(r) : "l"(a), "l"(b)); return r;
}
__device__ __forceinline__ u64 fma2(u64 a, u64 b, u64 c) {
    u64 r; asm("fma.rn.f32x2 %0, %1, %2, %3;" : "=l"(r) : "l"(a), "l"(b), "l"(c)); return r;
}

__global__ __launch_bounds__(256, 4) void gat_kernel(
    const float* __restrict__ item,
    const float* __restrict__ ent,
    const int*   __restrict__ adj,
    const float* __restrict__ W,
    const float* __restrict__ a,
    float*       __restrict__ out)
{
    __shared__ float wa1s[64], wa2s[64];
    __shared__ float dbuf[2][64];
    __shared__ float xbufd[2][128];    // x duplicated {x,x}, transposed: pair index (m&7)*8+(m>>3)
    __shared__ float part[2][256];
    __shared__ float smsum[2][2][2];   // [group][row parity][warp 0/1]
    __shared__ float s1buf[2];

    const int t    = threadIdx.x;
    const int gi   = t >> 7;
    const int gt   = t & 127;
    const int lane = t & 31;
    const int wg   = gt >> 5;
    const int mB   = gt >> 4;          // 0..7
    const int fe   = gt - 64;          // epilogue f (wg>=2)
    const int barid = 1 + gi;

    // --- wa1 = W@a1, wa2 = W@a2 (once per CTA) ---
    {
        const int f = t >> 2, q = t & 3;
        const float* wr = W + f * 64 + q * 16;
        float p1 = 0.f, p2 = 0.f;
#pragma unroll
        for (int i = 0; i < 4; ++i) {
            float4 wv = *(const float4*)(wr + i * 4);
            float4 y1 = *(const float4*)(a + q * 16 + i * 4);
            float4 y2 = *(const float4*)(a + 64 + q * 16 + i * 4);
            p1 += wv.x*y1.x + wv.y*y1.y + wv.z*y1.z + wv.w*y1.w;
            p2 += wv.x*y2.x + wv.y*y2.y + wv.z*y2.z + wv.w*y2.w;
        }
        p1 += __shfl_xor_sync(~0u, p1, 1); p1 += __shfl_xor_sync(~0u, p1, 2);
        p2 += __shfl_xor_sync(~0u, p2, 1); p2 += __shfl_xor_sync(~0u, p2, 2);
        if (q == 0) { wa1s[f] = p1; wa2s[f] = p2; }
    }
    __syncthreads();
    const float4 w2f = *(const float4*)&wa2s[(gt & 15) * 4];
    const u64 w2lo = pk2(w2f.x, w2f.y);
    const u64 w2hi = pk2(w2f.z, w2f.w);

    int n   = blockIdx.x * 2 + gi;
    int off = n * 64;

    // --- Prime row n: masks + tile; masks for n+1 ---
    unsigned bm0, bm1, nx0 = 0, nx1 = 0;
    {
        const int a0 = adj[off + lane], a1 = adj[off + 32 + lane];
        bm0 = __ballot_sync(~0u, a0 > 0);
        bm1 = __ballot_sync(~0u, a1 > 0);
    }
    ulonglong2 v[8];
    {
        const float* eb = ent + (size_t)off * 64;
#pragma unroll
        for (int c = 0; c < 8; ++c) {
            const int m = mB + 8 * c;
            const bool lv = (m < 32) ? ((bm0 >> m) & 1u) : ((bm1 >> (m - 32)) & 1u);
            v[c] = lv ? *(const ulonglong2*)(eb + (size_t)(gt + 128 * c) * 4)
                      : make_ulonglong2(0ull, 0ull);
        }
    }
    bool hasN = (n + NGROUP) < N_ITEMS;
    if (hasN) {
        const int a0 = adj[off + S64 + lane], a1 = adj[off + S64 + 32 + lane];
        nx0 = __ballot_sync(~0u, a0 > 0);
        nx1 = __ballot_sync(~0u, a1 > 0);
    }
    float ia = 0.f, ib = 0.f, iePrev = 0.f, ieCur = 0.f;
    if (wg == 2) { ia = item[off + lane]; ib = item[off + 32 + lane]; }
    if (wg >= 2) { ieCur = item[off + fe]; }

    int par = 0, offPrev = -1;

    while (true) {
        // ---- window A: d-phase (packed) + s1 (warp 2) ----
        float dd[8];
#pragma unroll
        for (int c = 0; c < 8; ++c) {
            const u64 tp = fma2(v[c].y, w2hi, mul2(v[c].x, w2lo));
            const float2 th = unpk2(tp);
            dd[c] = th.x + th.y;
        }
        float e0 = ((lane&1)? dd[1]:dd[0]) + __shfl_xor_sync(~0u, (lane&1)? dd[0]:dd[1], 1);
        float e1 = ((lane&1)? dd[3]:dd[2]) + __shfl_xor_sync(~0u, (lane&1)? dd[2]:dd[3], 1);
        float e2 = ((lane&1)? dd[5]:dd[4]) + __shfl_xor_sync(~0u, (lane&1)? dd[4]:dd[5], 1);
        float e3 = ((lane&1)? dd[7]:dd[6]) + __shfl_xor_sync(~0u, (lane&1)? dd[6]:dd[7], 1);
        float f0 = ((lane&2)? e1:e0) + __shfl_xor_sync(~0u, (lane&2)? e0:e1, 2);
        float f1 = ((lane&2)? e3:e2) + __shfl_xor_sync(~0u, (lane&2)? e2:e3, 2);
        float g0 = ((lane&4)? f1:f0) + __shfl_xor_sync(~0u, (lane&4)? f0:f1, 4);
        g0 += __shfl_xor_sync(~0u, g0, 8);
        if (!(lane & 8)) dbuf[gi][mB + 8 * (lane & 7)] = g0;
        if (wg == 2) {
            float p = ia * wa1s[lane] + ib * wa1s[32 + lane];
            p += __shfl_xor_sync(~0u, p, 16);
            p += __shfl_xor_sync(~0u, p, 8);
            p += __shfl_xor_sync(~0u, p, 4);
            p += __shfl_xor_sync(~0u, p, 2);
            p += __shfl_xor_sync(~0u, p, 1);
            if (lane == 0) s1buf[gi] = p;
        }
        BARG();

        // ---- window B: wg0-1: x + sum; wg2-3: prev epilogue + item prefetch ----
        if (wg < 2) {
            float e = s1buf[gi] + dbuf[gi][gt];
            e = fmaxf(e, ALPHA * e);
            const unsigned mk = wg ? bm1 : bm0;
            const float x = ((mk >> lane) & 1u) ? __expf(e) : 0.f;
            // duplicated, transposed store: pair index (m&7)*8 + (m>>3)
            *(float2*)&xbufd[gi][(((gt & 7) * 8) + (gt >> 3)) * 2] = make_float2(x, x);
            float sm = x;
            sm += __shfl_xor_sync(~0u, sm, 16);
            sm += __shfl_xor_sync(~0u, sm, 8);
            sm += __shfl_xor_sync(~0u, sm, 4);
            sm += __shfl_xor_sync(~0u, sm, 2);
            sm += __shfl_xor_sync(~0u, sm, 1);
            if (lane == 0) smsum[gi][par][wg] = sm;
        } else {
            if (offPrev >= 0) {
                const float r = (part[gi][fe] + part[gi][64 + fe])
                              + (part[gi][128 + fe] + part[gi][192 + fe]);
                const float inv = 1.0f / (smsum[gi][par ^ 1][0] + smsum[gi][par ^ 1][1]);
                out[offPrev + fe] = r * inv + iePrev;
            }
            iePrev = ieCur;
            if (hasN) {
                ieCur = item[off + S64 + fe];
                if (wg == 2) { ia = item[off + S64 + lane]; ib = item[off + S64 + 32 + lane]; }
            }
        }
        BARG();

        // ---- window C: packed acc(current) + next-row tile loads ----
        const bool hasNN = (n + 2 * NGROUP) < N_ITEMS;
        {
            const float* ebN = ent + (size_t)(off + S64) * 64;
            // 4x LDS.128: x pairs for c=0..7 (broadcast within 16-lane groups)
            const ulonglong2 xq01 = *(const ulonglong2*)&xbufd[gi][mB * 16];
            const ulonglong2 xq23 = *(const ulonglong2*)&xbufd[gi][mB * 16 + 4];
            const ulonglong2 xq45 = *(const ulonglong2*)&xbufd[gi][mB * 16 + 8];
            const ulonglong2 xq67 = *(const ulonglong2*)&xbufd[gi][mB * 16 + 12];
            u64 axy = 0ull, azw = 0ull;   // {0.f,0.f}
            axy = fma2(xq01.x, v[0].x, axy); azw = fma2(xq01.x, v[0].y, azw);
            axy = fma2(xq01.y, v[1].x, axy); azw = fma2(xq01.y, v[1].y, azw);
            axy = fma2(xq23.x, v[2].x, axy); azw = fma2(xq23.x, v[2].y, azw);
            axy = fma2(xq23.y, v[3].x, axy); azw = fma2(xq23.y, v[3].y, azw);
            axy = fma2(xq45.x, v[4].x, axy); azw = fma2(xq45.x, v[4].y, azw);
            axy = fma2(xq45.y, v[5].x, axy); azw = fma2(xq45.y, v[5].y, azw);
            axy = fma2(xq67.x, v[6].x, axy); azw = fma2(xq67.x, v[6].y, azw);
            axy = fma2(xq67.y, v[7].x, axy); azw = fma2(xq67.y, v[7].y, azw);
            // next-row tile loads (predicated)
#pragma unroll
            for (int c = 0; c < 8; ++c) {
                const int m = mB + 8 * c;
                const bool lv = hasN && ((m < 32) ? ((nx0 >> m) & 1u)
                                                  : ((nx1 >> (m - 32)) & 1u));
                v[c] = lv ? *(const ulonglong2*)(ebN + (size_t)(gt + 128 * c) * 4)
                          : make_ulonglong2(0ull, 0ull);
            }
            float2 pxy = unpk2(axy), pzw = unpk2(azw);
            pxy.x += __shfl_xor_sync(~0u, pxy.x, 16);
            pxy.y += __shfl_xor_sync(~0u, pxy.y, 16);
            pzw.x += __shfl_xor_sync(~0u, pzw.x, 16);
            pzw.y += __shfl_xor_sync(~0u, pzw.y, 16);
            if (lane < 16) {
                float4 st = make_float4(pxy.x, pxy.y, pzw.x, pzw.y);
                *(float4*)&part[gi][wg * 64 + lane * 4] = st;
            }
        }
        bm0 = nx0; bm1 = nx1;
        if (hasNN) {
            const int a0 = adj[off + 2 * S64 + lane];
            const int a1 = adj[off + 2 * S64 + 32 + lane];
            nx0 = __ballot_sync(~0u, a0 > 0);
            nx1 = __ballot_sync(~0u, a1 > 0);
        } else { nx0 = 0; nx1 = 0; }

        offPrev = off; off += S64; n += NGROUP; par ^= 1; hasN = hasNN;
        if (n >= N_ITEMS) break;
    }

    // ---- drain: epilogue for the final row ----
    BARG();
    if (wg >= 2) {
        const float r = (part[gi][fe] + part[gi][64 + fe])
                      + (part[gi][128 + fe] + part[gi][192 + fe]);
        const float inv = 1.0f / (smsum[gi][par ^ 1][0] + smsum[gi][par ^ 1][1]);
        out[offPrev + fe] = r * inv + iePrev;
    }
}

extern "C" void kernel_launch(void* const* d_in, const int* in_sizes, int n_in,
                              void* d_out, int out_size) {
    const float* item = (const float*)d_in[0];
    const float* ent  = (const float*)d_in[1];
    const int*   adj  = (const int*)d_in[2];
    const float* W    = (const float*)d_in[3];
    const float* a    = (const float*)d_in[4];
    float* out = (float*)d_out;

    gat_kernel<<<GRID, 256>>>(item, ent, adj, W, a, out);
}